// round 1
// baseline (speedup 1.0000x reference)
#include <cuda_runtime.h>
#include <cstddef>

#define PR_N      16384
#define PR_INDIM  256
#define PR_OUTDIM 128
#define BM        64
#define BN        64

// Scratch for Q/K/V projections (8 MB each). __device__ globals: allowed scratch.
__device__ float g_Q[PR_N * PR_OUTDIM];
__device__ float g_K[PR_N * PR_OUTDIM];
__device__ float g_V[PR_N * PR_OUTDIM];

// ---------------------------------------------------------------------------
// Kernel 1: QKV projection.  grid = N/64, block = 256.
// Per CTA: rows [rb, rb+64).  Thread (tr,tc) owns rows 4*tr+i, cols tc+16*c.
// ---------------------------------------------------------------------------
__global__ void __launch_bounds__(256) pr_proj_kernel(
    const float* __restrict__ x,
    const float* __restrict__ Wq, const float* __restrict__ bq,
    const float* __restrict__ Wk, const float* __restrict__ bk,
    const float* __restrict__ Wv, const float* __restrict__ bv)
{
    __shared__ float xs[BM * PR_INDIM];   // 64 KB
    __shared__ float ws[64 * PR_OUTDIM];  // 32 KB (one 64-row W chunk)

    const int t  = threadIdx.x;
    const int rb = blockIdx.x * BM;
    const int tr = t >> 4;       // 0..15 -> rows 4*tr..4*tr+3
    const int tc = t & 15;       // 0..15 -> cols tc, tc+16, ..., tc+112

    // Load x tile [64 x 256] (row-major), coalesced float4.
    {
        const float4* xg  = (const float4*)(x + (size_t)rb * PR_INDIM);
        float4*       xs4 = (float4*)xs;
#pragma unroll
        for (int i = 0; i < 16; i++) xs4[t + i * 256] = xg[t + i * 256];
    }

    const float* Wm[3] = {Wq, Wk, Wv};
    const float* bm[3] = {bq, bk, bv};
    float*       Om[3] = {g_Q, g_K, g_V};

#pragma unroll 1
    for (int m = 0; m < 3; m++) {
        float acc[4][8];
#pragma unroll
        for (int c = 0; c < 8; c++) {
            float b = bm[m][tc + 16 * c];
#pragma unroll
            for (int i = 0; i < 4; i++) acc[i][c] = b;
        }

        for (int kb = 0; kb < PR_INDIM; kb += 64) {
            __syncthreads();  // ws reuse (and first-iter: xs ready)
            {
                const float4* wg  = (const float4*)(Wm[m] + (size_t)kb * PR_OUTDIM);
                float4*       ws4 = (float4*)ws;
#pragma unroll
                for (int i = 0; i < 8; i++) ws4[t + i * 256] = wg[t + i * 256];
            }
            __syncthreads();

#pragma unroll 4
            for (int k = 0; k < 64; k++) {
                float xv[4];
#pragma unroll
                for (int i = 0; i < 4; i++)
                    xv[i] = xs[(4 * tr + i) * PR_INDIM + kb + k];  // broadcast
                float wv[8];
#pragma unroll
                for (int c = 0; c < 8; c++)
                    wv[c] = ws[k * PR_OUTDIM + tc + 16 * c];        // conflict-free
#pragma unroll
                for (int i = 0; i < 4; i++)
#pragma unroll
                    for (int c = 0; c < 8; c++)
                        acc[i][c] = fmaf(xv[i], wv[c], acc[i][c]);
            }
        }

        float* O = Om[m] + (size_t)rb * PR_OUTDIM;
#pragma unroll
        for (int i = 0; i < 4; i++)
#pragma unroll
            for (int c = 0; c < 8; c++)
                O[(4 * tr + i) * PR_OUTDIM + tc + 16 * c] = acc[i][c];
    }
}

// ---------------------------------------------------------------------------
// Kernel 2: streaming attention, single pass (no max subtraction: |logit|<~60,
// exp() and the running sums stay well inside fp32 range).
// grid = N/64, block = 256, dynamic smem ~113 KB.
//
// Thread (tr,tc):
//   S stage : rows 4*tr+i (i<4), key cols tc+16*j (j<4)   -> s[4][4]
//   PV stage: rows 4*tr+i, out cols 8*tc..8*tc+7           -> oacc[4][8]
//   lacc[i] : partial row sums of exp, reduced over the 16 tc lanes at the end.
// Ks padded to stride 132 floats so the 16 lanes (rows tc+16j) hit distinct
// bank groups on LDS.128.
// ---------------------------------------------------------------------------
#define QS_STRIDE 128
#define KS_STRIDE 132
#define VS_STRIDE 128
#define PS_STRIDE 64
#define SMEM_FLOATS (BM * QS_STRIDE + BN * KS_STRIDE + BN * VS_STRIDE + BM * PS_STRIDE)

__global__ void __launch_bounds__(256) pr_attn_kernel(float* __restrict__ out)
{
    extern __shared__ float sm[];
    float* Qs = sm;                       // 64 x 128
    float* Ks = Qs + BM * QS_STRIDE;      // 64 x 132
    float* Vs = Ks + BN * KS_STRIDE;      // 64 x 128
    float* Ps = Vs + BN * VS_STRIDE;      // 64 x 64

    const int t  = threadIdx.x;
    const int tr = t >> 4;
    const int tc = t & 15;
    const int qb = blockIdx.x * BM;

    // Load Q tile once.
    {
        const float4* qg  = (const float4*)(g_Q + (size_t)qb * PR_OUTDIM);
        float4*       qs4 = (float4*)Qs;
#pragma unroll
        for (int i = 0; i < 8; i++) qs4[t + i * 256] = qg[t + i * 256];
    }

    float oacc[4][8];
#pragma unroll
    for (int i = 0; i < 4; i++)
#pragma unroll
        for (int c = 0; c < 8; c++) oacc[i][c] = 0.0f;
    float lacc[4] = {0.0f, 0.0f, 0.0f, 0.0f};

    for (int kb = 0; kb < PR_N; kb += BN) {
        __syncthreads();  // protect Ks/Vs/Ps from previous iteration's readers
        {
            const float4* kg = (const float4*)(g_K + (size_t)kb * PR_OUTDIM);
#pragma unroll
            for (int ii = 0; ii < 8; ii++) {
                int i = t + ii * 256;
                int r = i >> 5, c = i & 31;
                ((float4*)Ks)[r * (KS_STRIDE / 4) + c] = kg[i];
            }
            const float4* vg = (const float4*)(g_V + (size_t)kb * PR_OUTDIM);
#pragma unroll
            for (int ii = 0; ii < 8; ii++)
                ((float4*)Vs)[t + ii * 256] = vg[t + ii * 256];
        }
        __syncthreads();

        // ---- S = Q Kt (this CTA's 64x64 tile) ----
        float s[4][4];
#pragma unroll
        for (int i = 0; i < 4; i++)
#pragma unroll
            for (int j = 0; j < 4; j++) s[i][j] = 0.0f;

        const float4* Qs4 = (const float4*)Qs;
        const float4* Ks4 = (const float4*)Ks;
#pragma unroll 8
        for (int d4 = 0; d4 < 32; d4++) {
            float4 qv[4], kv[4];
#pragma unroll
            for (int i = 0; i < 4; i++)
                qv[i] = Qs4[(4 * tr + i) * (QS_STRIDE / 4) + d4];
#pragma unroll
            for (int j = 0; j < 4; j++)
                kv[j] = Ks4[(tc + 16 * j) * (KS_STRIDE / 4) + d4];
#pragma unroll
            for (int i = 0; i < 4; i++)
#pragma unroll
                for (int j = 0; j < 4; j++) {
                    s[i][j] = fmaf(qv[i].x, kv[j].x, s[i][j]);
                    s[i][j] = fmaf(qv[i].y, kv[j].y, s[i][j]);
                    s[i][j] = fmaf(qv[i].z, kv[j].z, s[i][j]);
                    s[i][j] = fmaf(qv[i].w, kv[j].w, s[i][j]);
                }
        }

        // ---- exp, accumulate row-sum partials, stage P ----
#pragma unroll
        for (int i = 0; i < 4; i++)
#pragma unroll
            for (int j = 0; j < 4; j++) {
                float e = __expf(s[i][j]);
                lacc[i] += e;
                Ps[(4 * tr + i) * PS_STRIDE + tc + 16 * j] = e;
            }
        __syncthreads();

        // ---- O += P V ----
        const float4* Vs4 = (const float4*)Vs;
#pragma unroll 4
        for (int j = 0; j < BN; j++) {
            float p[4];
#pragma unroll
            for (int i = 0; i < 4; i++)
                p[i] = Ps[(4 * tr + i) * PS_STRIDE + j];  // broadcast
            float4 v0 = Vs4[j * (VS_STRIDE / 4) + tc * 2];
            float4 v1 = Vs4[j * (VS_STRIDE / 4) + tc * 2 + 1];
#pragma unroll
            for (int i = 0; i < 4; i++) {
                oacc[i][0] = fmaf(p[i], v0.x, oacc[i][0]);
                oacc[i][1] = fmaf(p[i], v0.y, oacc[i][1]);
                oacc[i][2] = fmaf(p[i], v0.z, oacc[i][2]);
                oacc[i][3] = fmaf(p[i], v0.w, oacc[i][3]);
                oacc[i][4] = fmaf(p[i], v1.x, oacc[i][4]);
                oacc[i][5] = fmaf(p[i], v1.y, oacc[i][5]);
                oacc[i][6] = fmaf(p[i], v1.z, oacc[i][6]);
                oacc[i][7] = fmaf(p[i], v1.w, oacc[i][7]);
            }
        }
    }

    // Reduce lacc across the 16 tc lanes (they sit in one half-warp: xor stays inside).
#pragma unroll
    for (int mask = 8; mask >= 1; mask >>= 1)
#pragma unroll
        for (int i = 0; i < 4; i++)
            lacc[i] += __shfl_xor_sync(0xffffffffu, lacc[i], mask);

#pragma unroll
    for (int i = 0; i < 4; i++) {
        float inv = 1.0f / lacc[i];
        float4 o0, o1;
        o0.x = oacc[i][0] * inv; o0.y = oacc[i][1] * inv;
        o0.z = oacc[i][2] * inv; o0.w = oacc[i][3] * inv;
        o1.x = oacc[i][4] * inv; o1.y = oacc[i][5] * inv;
        o1.z = oacc[i][6] * inv; o1.w = oacc[i][7] * inv;
        float4* op = (float4*)(out + (size_t)(qb + 4 * tr + i) * PR_OUTDIM + 8 * tc);
        op[0] = o0;
        op[1] = o1;
    }
}

// ---------------------------------------------------------------------------
// Launch: proj -> attn, default stream (graph-capturable, allocation-free).
// ---------------------------------------------------------------------------
extern "C" void kernel_launch(void* const* d_in, const int* in_sizes, int n_in,
                              void* d_out, int out_size)
{
    const float* x  = (const float*)d_in[0];
    const float* Wq = (const float*)d_in[1];
    const float* bq = (const float*)d_in[2];
    const float* Wk = (const float*)d_in[3];
    const float* bk = (const float*)d_in[4];
    const float* Wv = (const float*)d_in[5];
    const float* bv = (const float*)d_in[6];
    float* out = (float*)d_out;

    pr_proj_kernel<<<PR_N / BM, 256>>>(x, Wq, bq, Wk, bk, Wv, bv);

    const int smem_bytes = SMEM_FLOATS * (int)sizeof(float);  // 115712 B
    cudaFuncSetAttribute(pr_attn_kernel,
                         cudaFuncAttributeMaxDynamicSharedMemorySize, smem_bytes);
    pr_attn_kernel<<<PR_N / BM, 256, smem_bytes>>>(out);
}

// round 3
// speedup vs baseline: 3.5359x; 3.5359x over previous
#include <cuda_runtime.h>
#include <cuda_bf16.h>
#include <cstdint>
#include <cstddef>

#define PR_N      16384
#define PR_INDIM  256
#define PR_D      128

// ---------------- bf16 split scratch (hi+lo ~= 16-bit mantissa fp32) --------
__device__ __align__(16) __nv_bfloat16 g_Qhi[PR_N * PR_D];
__device__ __align__(16) __nv_bfloat16 g_Qlo[PR_N * PR_D];
__device__ __align__(16) __nv_bfloat16 g_Khi[PR_N * PR_D];
__device__ __align__(16) __nv_bfloat16 g_Klo[PR_N * PR_D];
__device__ __align__(16) __nv_bfloat16 g_VThi[PR_D * PR_N];  // V transposed [d][n]
__device__ __align__(16) __nv_bfloat16 g_VTlo[PR_D * PR_N];

// ---------------- helpers ---------------------------------------------------
__device__ __forceinline__ uint32_t smem_u32(const void* p) {
    uint32_t a;
    asm("{ .reg .u64 t; cvta.to.shared.u64 t, %1; cvt.u32.u64 %0, t; }"
        : "=r"(a) : "l"(p));
    return a;
}
// pack two fp32 -> bf16x2 (a in low half, b in high half)
__device__ __forceinline__ uint32_t pack_bf16x2(float a, float b) {
    uint32_t r;
    asm("cvt.rn.satfinite.bf16x2.f32 %0, %1, %2;" : "=r"(r) : "f"(b), "f"(a));
    return r;
}
__device__ __forceinline__ void split2(float f0, float f1, uint32_t& hi, uint32_t& lo) {
    hi = pack_bf16x2(f0, f1);
    float h0 = __uint_as_float(hi << 16);
    float h1 = __uint_as_float(hi & 0xffff0000u);
    lo = pack_bf16x2(f0 - h0, f1 - h1);
}

__device__ __forceinline__ void ldmx4(uint32_t* r, uint32_t addr) {
    asm volatile("ldmatrix.sync.aligned.m8n8.x4.shared.b16 {%0,%1,%2,%3}, [%4];"
                 : "=r"(r[0]), "=r"(r[1]), "=r"(r[2]), "=r"(r[3]) : "r"(addr));
}
__device__ __forceinline__ void mma16816(float* c, const uint32_t* a,
                                         const uint32_t* b) {
    asm volatile(
        "mma.sync.aligned.m16n8k16.row.col.f32.bf16.bf16.f32 "
        "{%0,%1,%2,%3}, {%4,%5,%6,%7}, {%8,%9}, {%0,%1,%2,%3};"
        : "+f"(c[0]), "+f"(c[1]), "+f"(c[2]), "+f"(c[3])
        : "r"(a[0]), "r"(a[1]), "r"(a[2]), "r"(a[3]), "r"(b[0]), "r"(b[1]));
}
__device__ __forceinline__ void cp16(uint32_t dst, const void* src) {
    asm volatile("cp.async.cg.shared.global [%0], [%1], 16;"
                 :: "r"(dst), "l"(src) : "memory");
}
__device__ __forceinline__ void cp_commit_wait_all() {
    asm volatile("cp.async.commit_group;" ::: "memory");
    asm volatile("cp.async.wait_group 0;" ::: "memory");
}

// ---------------------------------------------------------------------------
// Kernel 1: QKV projection + bf16 split + V transpose.  grid=256, block=256.
// ---------------------------------------------------------------------------
__global__ void __launch_bounds__(256) pr_proj_kernel(
    const float* __restrict__ x,
    const float* __restrict__ Wq, const float* __restrict__ bq,
    const float* __restrict__ Wk, const float* __restrict__ bk,
    const float* __restrict__ Wv, const float* __restrict__ bv)
{
    __shared__ float xs[64 * PR_INDIM];  // 64 KB
    __shared__ float ws[64 * 132];       // W chunk (stride 128) / staging (stride 132)

    const int t  = threadIdx.x;
    const int rb = blockIdx.x * 64;
    const int tr = t >> 4;
    const int tc = t & 15;

    {
        const float4* xg  = (const float4*)(x + (size_t)rb * PR_INDIM);
        float4*       xs4 = (float4*)xs;
#pragma unroll
        for (int i = 0; i < 16; i++) xs4[t + i * 256] = xg[t + i * 256];
    }

    const float* Wm[3] = {Wq, Wk, Wv};
    const float* bm[3] = {bq, bk, bv};

#pragma unroll 1
    for (int m = 0; m < 3; m++) {
        float acc[4][8];
#pragma unroll
        for (int c = 0; c < 8; c++) {
            float b = bm[m][tc + 16 * c];
#pragma unroll
            for (int i = 0; i < 4; i++) acc[i][c] = b;
        }

        for (int kb = 0; kb < PR_INDIM; kb += 64) {
            __syncthreads();
            {
                const float4* wg  = (const float4*)(Wm[m] + (size_t)kb * PR_D);
                float4*       ws4 = (float4*)ws;
#pragma unroll
                for (int i = 0; i < 8; i++) ws4[t + i * 256] = wg[t + i * 256];
            }
            __syncthreads();
#pragma unroll 4
            for (int k = 0; k < 64; k++) {
                float xv[4];
#pragma unroll
                for (int i = 0; i < 4; i++)
                    xv[i] = xs[(4 * tr + i) * PR_INDIM + kb + k];
                float wv[8];
#pragma unroll
                for (int c = 0; c < 8; c++)
                    wv[c] = ws[k * PR_D + tc + 16 * c];
#pragma unroll
                for (int i = 0; i < 4; i++)
#pragma unroll
                    for (int c = 0; c < 8; c++)
                        acc[i][c] = fmaf(xv[i], wv[c], acc[i][c]);
            }
        }

        // stage fp32 result (stride 132 dodges conflicts)
        __syncthreads();
#pragma unroll
        for (int i = 0; i < 4; i++)
#pragma unroll
            for (int c = 0; c < 8; c++)
                ws[(4 * tr + i) * 132 + tc + 16 * c] = acc[i][c];
        __syncthreads();

        if (m < 2) {
            __nv_bfloat16* Dh = (m == 0) ? g_Qhi : g_Khi;
            __nv_bfloat16* Dl = (m == 0) ? g_Qlo : g_Klo;
            const int r  = t >> 2;
            const int cb = (t & 3) * 32;
            uint32_t hi[16], lo[16];
#pragma unroll
            for (int j = 0; j < 16; j++)
                split2(ws[r * 132 + cb + 2 * j], ws[r * 132 + cb + 2 * j + 1], hi[j], lo[j]);
            uint4* dh = (uint4*)(Dh + (size_t)(rb + r) * PR_D + cb);
            uint4* dl = (uint4*)(Dl + (size_t)(rb + r) * PR_D + cb);
#pragma unroll
            for (int q = 0; q < 4; q++) {
                dh[q] = make_uint4(hi[4*q], hi[4*q+1], hi[4*q+2], hi[4*q+3]);
                dl[q] = make_uint4(lo[4*q], lo[4*q+1], lo[4*q+2], lo[4*q+3]);
            }
        } else {
            // V: transpose to [d][n]
            const int d    = t >> 1;
            const int half = t & 1;
            uint32_t hi[16], lo[16];
#pragma unroll
            for (int j = 0; j < 16; j++) {
                int k0 = 32 * half + 2 * j;
                split2(ws[k0 * 132 + d], ws[(k0 + 1) * 132 + d], hi[j], lo[j]);
            }
            uint4* dh = (uint4*)(g_VThi + (size_t)d * PR_N + rb + 32 * half);
            uint4* dl = (uint4*)(g_VTlo + (size_t)d * PR_N + rb + 32 * half);
#pragma unroll
            for (int q = 0; q < 4; q++) {
                dh[q] = make_uint4(hi[4*q], hi[4*q+1], hi[4*q+2], hi[4*q+3]);
                dl[q] = make_uint4(lo[4*q], lo[4*q+1], lo[4*q+2], lo[4*q+3]);
            }
        }
        __syncthreads();
    }
}

// ---------------------------------------------------------------------------
// Kernel 2: HMMA (mma.sync) flash attention, split-bf16 (3 MMA passes),
// no max-subtraction.  grid=128 CTAs x 256 thr.  Warp w: q rows [16w,16w+16).
// smem tiles padded to 272 B/row (17 chunks) -> ldmatrix conflict-free.
// ---------------------------------------------------------------------------
#define TROW   272           // padded row bytes (128 bf16 + 8 pad)
#define TBYTES (128 * TROW)  // 34816 per matrix
#define SM_QH  0
#define SM_QL  (1 * TBYTES)
#define SM_KH  (2 * TBYTES)
#define SM_KL  (3 * TBYTES)
#define SM_VH  (4 * TBYTES)
#define SM_VL  (5 * TBYTES)
#define SM_BYTES (6 * TBYTES)   // 208896

__device__ __forceinline__ void cp_tile(uint32_t dst, const __nv_bfloat16* src,
                                        int stride)
{
    const int t = threadIdx.x;
#pragma unroll
    for (int i = 0; i < 8; i++) {
        int cid = t + i * 256;           // 128 rows x 16 chunks
        int r = cid >> 4, c = cid & 15;
        cp16(dst + r * TROW + c * 16, src + (size_t)r * stride + c * 8);
    }
}

__global__ void __launch_bounds__(256, 1) pr_attn_mma(float* __restrict__ out)
{
    extern __shared__ char sm[];
    const uint32_t sb = smem_u32(sm);

    const int t    = threadIdx.x;
    const int w    = t >> 5;
    const int lane = t & 31;
    const int qb   = blockIdx.x * 128;

    // ldmatrix per-lane base addresses
    // A (Q / 16-row tiles): row = 16w + (lane&15), chunk = 2kc + (lane>>4)
    const uint32_t aRow = (uint32_t)(16 * w + (lane & 15));
    const uint32_t aCol = (uint32_t)(lane >> 4);
    const uint32_t aQh = sb + SM_QH + aRow * TROW + aCol * 16;
    const uint32_t aQl = sb + SM_QL + aRow * TROW + aCol * 16;
    // B (K / VT 16-row groups): row = (lane&7) + 8*(lane>>4), chunk = 2kc + ((lane>>3)&1)
    const uint32_t bRow = (uint32_t)((lane & 7) + 8 * (lane >> 4));
    const uint32_t bCol = (uint32_t)((lane >> 3) & 1);
    const uint32_t bKh = sb + SM_KH + bRow * TROW + bCol * 16;
    const uint32_t bKl = sb + SM_KL + bRow * TROW + bCol * 16;
    const uint32_t bVh = sb + SM_VH + bRow * TROW + bCol * 16;
    const uint32_t bVl = sb + SM_VL + bRow * TROW + bCol * 16;

    // Q tile: persistent in smem
    cp_tile(sb + SM_QH, g_Qhi + (size_t)qb * PR_D, PR_D);
    cp_tile(sb + SM_QL, g_Qlo + (size_t)qb * PR_D, PR_D);

    float o[16][4];
#pragma unroll
    for (int i = 0; i < 16; i++)
#pragma unroll
        for (int j = 0; j < 4; j++) o[i][j] = 0.0f;
    float lsum0 = 0.0f, lsum1 = 0.0f;

    for (int tt = 0; tt < PR_N / 128; tt++) {
        const int kb = tt * 128;
        __syncthreads();  // previous tile's smem readers done
        cp_tile(sb + SM_KH, g_Khi + (size_t)kb * PR_D, PR_D);
        cp_tile(sb + SM_KL, g_Klo + (size_t)kb * PR_D, PR_D);
        cp_tile(sb + SM_VH, g_VThi + kb, PR_N);
        cp_tile(sb + SM_VL, g_VTlo + kb, PR_N);
        cp_commit_wait_all();
        __syncthreads();

        // ---- S = Q K^T (hi*hi + lo*hi + hi*lo) ----
        float s[16][4];
#pragma unroll
        for (int i = 0; i < 16; i++)
#pragma unroll
            for (int j = 0; j < 4; j++) s[i][j] = 0.0f;

#pragma unroll 1
        for (int kc = 0; kc < 8; kc++) {
            uint32_t ah[4], al[4];
            ldmx4(ah, aQh + kc * 32);
            ldmx4(al, aQl + kc * 32);
#pragma unroll
            for (int jn = 0; jn < 8; jn++) {
                uint32_t bh[4], bl[4];
                ldmx4(bh, bKh + jn * (16 * TROW) + kc * 32);
                ldmx4(bl, bKl + jn * (16 * TROW) + kc * 32);
                mma16816(s[2 * jn],     ah, &bh[0]);
                mma16816(s[2 * jn],     al, &bh[0]);
                mma16816(s[2 * jn],     ah, &bl[0]);
                mma16816(s[2 * jn + 1], ah, &bh[2]);
                mma16816(s[2 * jn + 1], al, &bh[2]);
                mma16816(s[2 * jn + 1], ah, &bl[2]);
            }
        }

        // ---- exp + split to bf16 P fragments (in place over s) ----
        uint32_t* ps = (uint32_t*)s;  // ps[4*jt + {0,1}]=hi pairs, {2,3}=lo pairs
#pragma unroll
        for (int jt = 0; jt < 16; jt++) {
            float e0 = __expf(s[jt][0]);
            float e1 = __expf(s[jt][1]);
            float e2 = __expf(s[jt][2]);
            float e3 = __expf(s[jt][3]);
            lsum0 += e0 + e1;
            lsum1 += e2 + e3;
            uint32_t h01, l01, h23, l23;
            split2(e0, e1, h01, l01);
            split2(e2, e3, h23, l23);
            ps[4 * jt + 0] = h01;
            ps[4 * jt + 1] = h23;
            ps[4 * jt + 2] = l01;
            ps[4 * jt + 3] = l23;
        }

        // ---- O += P V (Ph*Vh + Pl*Vh + Ph*Vl) ----
#pragma unroll
        for (int kc = 0; kc < 8; kc++) {
            uint32_t ah[4] = {ps[8 * kc + 0], ps[8 * kc + 1],
                              ps[8 * kc + 4], ps[8 * kc + 5]};
            uint32_t al[4] = {ps[8 * kc + 2], ps[8 * kc + 3],
                              ps[8 * kc + 6], ps[8 * kc + 7]};
#pragma unroll
            for (int dn = 0; dn < 8; dn++) {
                uint32_t bh[4], bl[4];
                ldmx4(bh, bVh + dn * (16 * TROW) + kc * 32);
                ldmx4(bl, bVl + dn * (16 * TROW) + kc * 32);
                mma16816(o[2 * dn],     ah, &bh[0]);
                mma16816(o[2 * dn],     al, &bh[0]);
                mma16816(o[2 * dn],     ah, &bl[0]);
                mma16816(o[2 * dn + 1], ah, &bh[2]);
                mma16816(o[2 * dn + 1], al, &bh[2]);
                mma16816(o[2 * dn + 1], ah, &bl[2]);
            }
        }
    }

    // ---- row-sum reduce across the 4 lanes sharing each row ----
    lsum0 += __shfl_xor_sync(0xffffffffu, lsum0, 1);
    lsum0 += __shfl_xor_sync(0xffffffffu, lsum0, 2);
    lsum1 += __shfl_xor_sync(0xffffffffu, lsum1, 1);
    lsum1 += __shfl_xor_sync(0xffffffffu, lsum1, 2);
    const float inv0 = 1.0f / lsum0;
    const float inv1 = 1.0f / lsum1;

    const int r0 = qb + 16 * w + (lane >> 2);
    const int cb = 2 * (lane & 3);
#pragma unroll
    for (int dt = 0; dt < 16; dt++) {
        float2 v0 = make_float2(o[dt][0] * inv0, o[dt][1] * inv0);
        float2 v1 = make_float2(o[dt][2] * inv1, o[dt][3] * inv1);
        *(float2*)(out + (size_t)r0 * PR_D + 8 * dt + cb)       = v0;
        *(float2*)(out + (size_t)(r0 + 8) * PR_D + 8 * dt + cb) = v1;
    }
}

// ---------------------------------------------------------------------------
extern "C" void kernel_launch(void* const* d_in, const int* in_sizes, int n_in,
                              void* d_out, int out_size)
{
    const float* x  = (const float*)d_in[0];
    const float* Wq = (const float*)d_in[1];
    const float* bq = (const float*)d_in[2];
    const float* Wk = (const float*)d_in[3];
    const float* bk = (const float*)d_in[4];
    const float* Wv = (const float*)d_in[5];
    const float* bv = (const float*)d_in[6];
    float* out = (float*)d_out;

    pr_proj_kernel<<<PR_N / 64, 256>>>(x, Wq, bq, Wk, bk, Wv, bv);

    cudaFuncSetAttribute(pr_attn_mma,
                         cudaFuncAttributeMaxDynamicSharedMemorySize, SM_BYTES);
    pr_attn_mma<<<PR_N / 128, 256, SM_BYTES>>>(out);
}

// round 4
// speedup vs baseline: 3.8402x; 1.0861x over previous
#include <cuda_runtime.h>
#include <cuda_bf16.h>
#include <cstdint>
#include <cstddef>

#define PR_N      16384
#define PR_INDIM  256
#define PR_D      128

// ---------------- bf16 split scratch (hi+lo ~= 16-bit mantissa fp32) --------
__device__ __align__(16) __nv_bfloat16 g_Qhi[PR_N * PR_D];
__device__ __align__(16) __nv_bfloat16 g_Qlo[PR_N * PR_D];
__device__ __align__(16) __nv_bfloat16 g_Khi[PR_N * PR_D];
__device__ __align__(16) __nv_bfloat16 g_Klo[PR_N * PR_D];
__device__ __align__(16) __nv_bfloat16 g_VThi[PR_D * PR_N];  // V transposed [d][n]
__device__ __align__(16) __nv_bfloat16 g_VTlo[PR_D * PR_N];

// ---------------- helpers ---------------------------------------------------
__device__ __forceinline__ uint32_t smem_u32(const void* p) {
    uint32_t a;
    asm("{ .reg .u64 t; cvta.to.shared.u64 t, %1; cvt.u32.u64 %0, t; }"
        : "=r"(a) : "l"(p));
    return a;
}
__device__ __forceinline__ uint32_t pack_bf16x2(float a, float b) {
    uint32_t r;
    asm("cvt.rn.satfinite.bf16x2.f32 %0, %1, %2;" : "=r"(r) : "f"(b), "f"(a));
    return r;
}
__device__ __forceinline__ void split2(float f0, float f1, uint32_t& hi, uint32_t& lo) {
    hi = pack_bf16x2(f0, f1);
    float h0 = __uint_as_float(hi << 16);
    float h1 = __uint_as_float(hi & 0xffff0000u);
    lo = pack_bf16x2(f0 - h0, f1 - h1);
}
__device__ __forceinline__ void ldmx4(uint32_t* r, uint32_t addr) {
    asm volatile("ldmatrix.sync.aligned.m8n8.x4.shared.b16 {%0,%1,%2,%3}, [%4];"
                 : "=r"(r[0]), "=r"(r[1]), "=r"(r[2]), "=r"(r[3]) : "r"(addr));
}
__device__ __forceinline__ void mma16816(float* c, const uint32_t* a,
                                         const uint32_t* b) {
    asm volatile(
        "mma.sync.aligned.m16n8k16.row.col.f32.bf16.bf16.f32 "
        "{%0,%1,%2,%3}, {%4,%5,%6,%7}, {%8,%9}, {%0,%1,%2,%3};"
        : "+f"(c[0]), "+f"(c[1]), "+f"(c[2]), "+f"(c[3])
        : "r"(a[0]), "r"(a[1]), "r"(a[2]), "r"(a[3]), "r"(b[0]), "r"(b[1]));
}
__device__ __forceinline__ void cp16(uint32_t dst, const void* src) {
    asm volatile("cp.async.cg.shared.global [%0], [%1], 16;"
                 :: "r"(dst), "l"(src) : "memory");
}
__device__ __forceinline__ void cp_commit() {
    asm volatile("cp.async.commit_group;" ::: "memory");
}
__device__ __forceinline__ void cp_wait2() {
    asm volatile("cp.async.wait_group 2;" ::: "memory");
}
__device__ __forceinline__ void cp_wait0() {
    asm volatile("cp.async.wait_group 0;" ::: "memory");
}

// ---------------------------------------------------------------------------
// Kernel 1: QKV projection + bf16 split + V transpose.  grid=256, block=256.
// ---------------------------------------------------------------------------
__global__ void __launch_bounds__(256) pr_proj_kernel(
    const float* __restrict__ x,
    const float* __restrict__ Wq, const float* __restrict__ bq,
    const float* __restrict__ Wk, const float* __restrict__ bk,
    const float* __restrict__ Wv, const float* __restrict__ bv)
{
    __shared__ float xs[64 * PR_INDIM];
    __shared__ float ws[64 * 132];

    const int t  = threadIdx.x;
    const int rb = blockIdx.x * 64;
    const int tr = t >> 4;
    const int tc = t & 15;

    {
        const float4* xg  = (const float4*)(x + (size_t)rb * PR_INDIM);
        float4*       xs4 = (float4*)xs;
#pragma unroll
        for (int i = 0; i < 16; i++) xs4[t + i * 256] = xg[t + i * 256];
    }

    const float* Wm[3] = {Wq, Wk, Wv};
    const float* bm[3] = {bq, bk, bv};

#pragma unroll 1
    for (int m = 0; m < 3; m++) {
        float acc[4][8];
#pragma unroll
        for (int c = 0; c < 8; c++) {
            float b = bm[m][tc + 16 * c];
#pragma unroll
            for (int i = 0; i < 4; i++) acc[i][c] = b;
        }

        for (int kb = 0; kb < PR_INDIM; kb += 64) {
            __syncthreads();
            {
                const float4* wg  = (const float4*)(Wm[m] + (size_t)kb * PR_D);
                float4*       ws4 = (float4*)ws;
#pragma unroll
                for (int i = 0; i < 8; i++) ws4[t + i * 256] = wg[t + i * 256];
            }
            __syncthreads();
#pragma unroll 4
            for (int k = 0; k < 64; k++) {
                float xv[4];
#pragma unroll
                for (int i = 0; i < 4; i++)
                    xv[i] = xs[(4 * tr + i) * PR_INDIM + kb + k];
                float wv[8];
#pragma unroll
                for (int c = 0; c < 8; c++)
                    wv[c] = ws[k * PR_D + tc + 16 * c];
#pragma unroll
                for (int i = 0; i < 4; i++)
#pragma unroll
                    for (int c = 0; c < 8; c++)
                        acc[i][c] = fmaf(xv[i], wv[c], acc[i][c]);
            }
        }

        __syncthreads();
#pragma unroll
        for (int i = 0; i < 4; i++)
#pragma unroll
            for (int c = 0; c < 8; c++)
                ws[(4 * tr + i) * 132 + tc + 16 * c] = acc[i][c];
        __syncthreads();

        if (m < 2) {
            __nv_bfloat16* Dh = (m == 0) ? g_Qhi : g_Khi;
            __nv_bfloat16* Dl = (m == 0) ? g_Qlo : g_Klo;
            const int r  = t >> 2;
            const int cb = (t & 3) * 32;
            uint32_t hi[16], lo[16];
#pragma unroll
            for (int j = 0; j < 16; j++)
                split2(ws[r * 132 + cb + 2 * j], ws[r * 132 + cb + 2 * j + 1], hi[j], lo[j]);
            uint4* dh = (uint4*)(Dh + (size_t)(rb + r) * PR_D + cb);
            uint4* dl = (uint4*)(Dl + (size_t)(rb + r) * PR_D + cb);
#pragma unroll
            for (int q = 0; q < 4; q++) {
                dh[q] = make_uint4(hi[4*q], hi[4*q+1], hi[4*q+2], hi[4*q+3]);
                dl[q] = make_uint4(lo[4*q], lo[4*q+1], lo[4*q+2], lo[4*q+3]);
            }
        } else {
            const int d    = t >> 1;
            const int half = t & 1;
            uint32_t hi[16], lo[16];
#pragma unroll
            for (int j = 0; j < 16; j++) {
                int k0 = 32 * half + 2 * j;
                split2(ws[k0 * 132 + d], ws[(k0 + 1) * 132 + d], hi[j], lo[j]);
            }
            uint4* dh = (uint4*)(g_VThi + (size_t)d * PR_N + rb + 32 * half);
            uint4* dl = (uint4*)(g_VTlo + (size_t)d * PR_N + rb + 32 * half);
#pragma unroll
            for (int q = 0; q < 4; q++) {
                dh[q] = make_uint4(hi[4*q], hi[4*q+1], hi[4*q+2], hi[4*q+3]);
                dl[q] = make_uint4(lo[4*q], lo[4*q+1], lo[4*q+2], lo[4*q+3]);
            }
        }
        __syncthreads();
    }
}

// ---------------------------------------------------------------------------
// Kernel 2: HMMA flash attention, split-bf16, 3-stage cp.async pipeline over
// 64-key subtiles, Q fragments register-resident.  grid=128 x 256 thr.
// ---------------------------------------------------------------------------
#define KROW   272                 // K tile row bytes (128 bf16 + pad)
#define VROW   144                 // VT tile row bytes (64 bf16 + pad)
#define OFF_KH 0
#define OFF_KL 17408               // 64*272
#define OFF_VH 34816
#define OFF_VL 53248               // 34816 + 128*144
#define ST_BYTES 71680             // stage size
#define N_STAGES 3
#define SM_BYTES (N_STAGES * ST_BYTES)   // 215040
#define NT (PR_N / 64)             // 256 subtiles

// issue one stage's cp.async (16 per thread)
__device__ __forceinline__ void load_stage(uint32_t dst, int kb)
{
    const int t = threadIdx.x;
#pragma unroll
    for (int i = 0; i < 4; i++) {
        int cid = t + i * 256;               // 1024: 64 rows x 16 chunks
        int r = cid >> 4, c = cid & 15;
        cp16(dst + OFF_KH + r * KROW + c * 16, g_Khi + (size_t)(kb + r) * PR_D + c * 8);
        cp16(dst + OFF_KL + r * KROW + c * 16, g_Klo + (size_t)(kb + r) * PR_D + c * 8);
    }
#pragma unroll
    for (int i = 0; i < 4; i++) {
        int cid = t + i * 256;               // 1024: 128 rows x 8 chunks
        int r = cid >> 3, c = cid & 7;
        cp16(dst + OFF_VH + r * VROW + c * 16, g_VThi + (size_t)r * PR_N + kb + c * 8);
        cp16(dst + OFF_VL + r * VROW + c * 16, g_VTlo + (size_t)r * PR_N + kb + c * 8);
    }
}

__global__ void __launch_bounds__(256, 1) pr_attn_mma(float* __restrict__ out)
{
    extern __shared__ char sm[];
    const uint32_t sb = smem_u32(sm);

    const int t    = threadIdx.x;
    const int w    = t >> 5;
    const int lane = t & 31;
    const int qb   = blockIdx.x * 128;

    // per-lane ldmatrix offsets
    const uint32_t aRow = (uint32_t)(16 * w + (lane & 15));
    const uint32_t aCol = (uint32_t)(lane >> 4);
    const uint32_t bRow = (uint32_t)((lane & 7) + 8 * (lane >> 4));
    const uint32_t bCol = (uint32_t)((lane >> 3) & 1);
    const uint32_t bKoff = bRow * KROW + bCol * 16;
    const uint32_t bVoff = bRow * VROW + bCol * 16;

    // ---- stage Q (hi at sb+0, lo at sb+34816, KROW rows) and grab fragments
    {
#pragma unroll
        for (int i = 0; i < 8; i++) {
            int cid = t + i * 256;           // 2048: 128 rows x 16 chunks
            int r = cid >> 4, c = cid & 15;
            cp16(sb + r * KROW + c * 16,        g_Qhi + (size_t)(qb + r) * PR_D + c * 8);
            cp16(sb + 34816 + r * KROW + c * 16, g_Qlo + (size_t)(qb + r) * PR_D + c * 8);
        }
        cp_commit();
        cp_wait0();
        __syncthreads();
    }
    uint32_t qh[8][4], ql[8][4];
    {
        const uint32_t aQ = sb + aRow * KROW + aCol * 16;
#pragma unroll
        for (int kc = 0; kc < 8; kc++) {
            ldmx4(qh[kc], aQ + kc * 32);
            ldmx4(ql[kc], aQ + 34816 + kc * 32);
        }
    }
    __syncthreads();

    float o[16][4];
#pragma unroll
    for (int i = 0; i < 16; i++)
#pragma unroll
        for (int j = 0; j < 4; j++) o[i][j] = 0.0f;
    float lsum0 = 0.0f, lsum1 = 0.0f;

    // prefetch tiles 0,1
    load_stage(sb + 0 * ST_BYTES, 0);
    cp_commit();
    load_stage(sb + 1 * ST_BYTES, 64);
    cp_commit();

    int st_cur = 0, st_pre = 2;
#pragma unroll 1
    for (int tt = 0; tt < NT; tt++) {
        __syncthreads();                 // prefetch target buffer free of readers
        if (tt + 2 < NT) load_stage(sb + st_pre * ST_BYTES, (tt + 2) * 64);
        cp_commit();
        cp_wait2();                      // oldest (tile tt) arrived
        __syncthreads();

        const uint32_t p   = sb + st_cur * ST_BYTES;
        const uint32_t bKh = p + OFF_KH + bKoff;
        const uint32_t bKl = p + OFF_KL + bKoff;
        const uint32_t bVh = p + OFF_VH + bVoff;
        const uint32_t bVl = p + OFF_VL + bVoff;

        // ---- S = Q K^T (hi*hi + lo*hi + hi*lo), 64 keys -> s[8][4]
        float s[8][4];
#pragma unroll
        for (int i = 0; i < 8; i++)
#pragma unroll
            for (int j = 0; j < 4; j++) s[i][j] = 0.0f;

#pragma unroll
        for (int kc = 0; kc < 8; kc++) {
#pragma unroll
            for (int jn = 0; jn < 4; jn++) {
                uint32_t bh[4], bl[4];
                ldmx4(bh, bKh + jn * (16 * KROW) + kc * 32);
                ldmx4(bl, bKl + jn * (16 * KROW) + kc * 32);
                // interleave the two accumulator chains for ILP
                mma16816(s[2 * jn],     qh[kc], &bh[0]);
                mma16816(s[2 * jn + 1], qh[kc], &bh[2]);
                mma16816(s[2 * jn],     ql[kc], &bh[0]);
                mma16816(s[2 * jn + 1], ql[kc], &bh[2]);
                mma16816(s[2 * jn],     qh[kc], &bl[0]);
                mma16816(s[2 * jn + 1], qh[kc], &bl[2]);
            }
        }

        // ---- exp + split to bf16 P fragments (in place)
        uint32_t* ps = (uint32_t*)s;
#pragma unroll
        for (int jt = 0; jt < 8; jt++) {
            float e0 = __expf(s[jt][0]);
            float e1 = __expf(s[jt][1]);
            float e2 = __expf(s[jt][2]);
            float e3 = __expf(s[jt][3]);
            lsum0 += e0 + e1;
            lsum1 += e2 + e3;
            uint32_t h01, l01, h23, l23;
            split2(e0, e1, h01, l01);
            split2(e2, e3, h23, l23);
            ps[4 * jt + 0] = h01;
            ps[4 * jt + 1] = h23;
            ps[4 * jt + 2] = l01;
            ps[4 * jt + 3] = l23;
        }

        // ---- O += P V (Ph*Vh + Pl*Vh + Ph*Vl), k-dim = 64 keys
#pragma unroll
        for (int kc = 0; kc < 4; kc++) {
            uint32_t ah[4] = {ps[8 * kc + 0], ps[8 * kc + 1],
                              ps[8 * kc + 4], ps[8 * kc + 5]};
            uint32_t al[4] = {ps[8 * kc + 2], ps[8 * kc + 3],
                              ps[8 * kc + 6], ps[8 * kc + 7]};
#pragma unroll
            for (int dn = 0; dn < 8; dn++) {
                uint32_t bh[4], bl[4];
                ldmx4(bh, bVh + dn * (16 * VROW) + kc * 32);
                ldmx4(bl, bVl + dn * (16 * VROW) + kc * 32);
                mma16816(o[2 * dn],     ah, &bh[0]);
                mma16816(o[2 * dn + 1], ah, &bh[2]);
                mma16816(o[2 * dn],     al, &bh[0]);
                mma16816(o[2 * dn + 1], al, &bh[2]);
                mma16816(o[2 * dn],     ah, &bl[0]);
                mma16816(o[2 * dn + 1], ah, &bl[2]);
            }
        }

        st_cur = (st_cur == 2) ? 0 : st_cur + 1;
        st_pre = (st_pre == 2) ? 0 : st_pre + 1;
    }

    // ---- row-sum reduce across the 4 lanes sharing each row
    lsum0 += __shfl_xor_sync(0xffffffffu, lsum0, 1);
    lsum0 += __shfl_xor_sync(0xffffffffu, lsum0, 2);
    lsum1 += __shfl_xor_sync(0xffffffffu, lsum1, 1);
    lsum1 += __shfl_xor_sync(0xffffffffu, lsum1, 2);
    const float inv0 = 1.0f / lsum0;
    const float inv1 = 1.0f / lsum1;

    const int r0 = qb + 16 * w + (lane >> 2);
    const int cb = 2 * (lane & 3);
#pragma unroll
    for (int dt = 0; dt < 16; dt++) {
        float2 v0 = make_float2(o[dt][0] * inv0, o[dt][1] * inv0);
        float2 v1 = make_float2(o[dt][2] * inv1, o[dt][3] * inv1);
        *(float2*)(out + (size_t)r0 * PR_D + 8 * dt + cb)       = v0;
        *(float2*)(out + (size_t)(r0 + 8) * PR_D + 8 * dt + cb) = v1;
    }
}

// ---------------------------------------------------------------------------
extern "C" void kernel_launch(void* const* d_in, const int* in_sizes, int n_in,
                              void* d_out, int out_size)
{
    const float* x  = (const float*)d_in[0];
    const float* Wq = (const float*)d_in[1];
    const float* bq = (const float*)d_in[2];
    const float* Wk = (const float*)d_in[3];
    const float* bk = (const float*)d_in[4];
    const float* Wv = (const float*)d_in[5];
    const float* bv = (const float*)d_in[6];
    float* out = (float*)d_out;

    pr_proj_kernel<<<PR_N / 64, 256>>>(x, Wq, bq, Wk, bk, Wv, bv);

    cudaFuncSetAttribute(pr_attn_mma,
                         cudaFuncAttributeMaxDynamicSharedMemorySize, SM_BYTES);
    pr_attn_mma<<<PR_N / 128, 256, SM_BYTES>>>(out);
}

// round 6
// speedup vs baseline: 5.0850x; 1.3242x over previous
#include <cuda_runtime.h>
#include <cuda_fp16.h>
#include <cstdint>
#include <cstddef>

#define PR_N      16384
#define PR_INDIM  256
#define PR_D      128
#define LOG2E     1.4426950408889634f

// ---------------- fp16 split scratch (hi+lo ~= 22-bit mantissa) -------------
__device__ __align__(16) __half g_Qhi[PR_N * PR_D];
__device__ __align__(16) __half g_Qlo[PR_N * PR_D];
__device__ __align__(16) __half g_Khi[PR_N * PR_D];
__device__ __align__(16) __half g_Klo[PR_N * PR_D];
__device__ __align__(16) __half g_VTh[PR_D * PR_N];   // V transposed [d][n], fp16

// ---------------- helpers ---------------------------------------------------
__device__ __forceinline__ uint32_t smem_u32(const void* p) {
    uint32_t a;
    asm("{ .reg .u64 t; cvta.to.shared.u64 t, %1; cvt.u32.u64 %0, t; }"
        : "=r"(a) : "l"(p));
    return a;
}
__device__ __forceinline__ float ex2f(float x) {   // MUFU.EX2
    float r;
    asm("ex2.approx.ftz.f32 %0, %1;" : "=f"(r) : "f"(x));
    return r;
}
// pack two fp32 -> fp16x2 (a low half, b high half)
__device__ __forceinline__ uint32_t pack_f16x2(float a, float b) {
    uint32_t r;
    asm("cvt.rn.f16x2.f32 %0, %1, %2;" : "=r"(r) : "f"(b), "f"(a));
    return r;
}
__device__ __forceinline__ void split2h(float f0, float f1, uint32_t& hi, uint32_t& lo) {
    __half a0 = __float2half_rn(f0), a1 = __float2half_rn(f1);
    hi = ((uint32_t)__half_as_ushort(a1) << 16) | __half_as_ushort(a0);
    lo = pack_f16x2(f0 - __half2float(a0), f1 - __half2float(a1));
}
__device__ __forceinline__ void ldmx4(uint32_t* r, uint32_t addr) {
    asm volatile("ldmatrix.sync.aligned.m8n8.x4.shared.b16 {%0,%1,%2,%3}, [%4];"
                 : "=r"(r[0]), "=r"(r[1]), "=r"(r[2]), "=r"(r[3]) : "r"(addr));
}
__device__ __forceinline__ void mma16816h(float* c, const uint32_t* a,
                                          const uint32_t* b) {
    asm volatile(
        "mma.sync.aligned.m16n8k16.row.col.f32.f16.f16.f32 "
        "{%0,%1,%2,%3}, {%4,%5,%6,%7}, {%8,%9}, {%0,%1,%2,%3};"
        : "+f"(c[0]), "+f"(c[1]), "+f"(c[2]), "+f"(c[3])
        : "r"(a[0]), "r"(a[1]), "r"(a[2]), "r"(a[3]), "r"(b[0]), "r"(b[1]));
}
__device__ __forceinline__ void cp16(uint32_t dst, const void* src) {
    asm volatile("cp.async.cg.shared.global [%0], [%1], 16;"
                 :: "r"(dst), "l"(src) : "memory");
}
__device__ __forceinline__ void cp_commit() {
    asm volatile("cp.async.commit_group;" ::: "memory");
}
__device__ __forceinline__ void cp_wait3() {
    asm volatile("cp.async.wait_group 3;" ::: "memory");
}
__device__ __forceinline__ void cp_wait0() {
    asm volatile("cp.async.wait_group 0;" ::: "memory");
}

// ---------------------------------------------------------------------------
// Kernel 1: QKV projection + fp16 split + V transpose.  grid=256, block=256.
// ---------------------------------------------------------------------------
__global__ void __launch_bounds__(256) pr_proj_kernel(
    const float* __restrict__ x,
    const float* __restrict__ Wq, const float* __restrict__ bq,
    const float* __restrict__ Wk, const float* __restrict__ bk,
    const float* __restrict__ Wv, const float* __restrict__ bv)
{
    __shared__ float xs[64 * PR_INDIM];
    __shared__ float ws[64 * 132];

    const int t  = threadIdx.x;
    const int rb = blockIdx.x * 64;
    const int tr = t >> 4;
    const int tc = t & 15;

    {
        const float4* xg  = (const float4*)(x + (size_t)rb * PR_INDIM);
        float4*       xs4 = (float4*)xs;
#pragma unroll
        for (int i = 0; i < 16; i++) xs4[t + i * 256] = xg[t + i * 256];
    }

    const float* Wm[3] = {Wq, Wk, Wv};
    const float* bm[3] = {bq, bk, bv};

#pragma unroll 1
    for (int m = 0; m < 3; m++) {
        float acc[4][8];
#pragma unroll
        for (int c = 0; c < 8; c++) {
            float b = bm[m][tc + 16 * c];
#pragma unroll
            for (int i = 0; i < 4; i++) acc[i][c] = b;
        }

        for (int kb = 0; kb < PR_INDIM; kb += 64) {
            __syncthreads();
            {
                const float4* wg  = (const float4*)(Wm[m] + (size_t)kb * PR_D);
                float4*       ws4 = (float4*)ws;
#pragma unroll
                for (int i = 0; i < 8; i++) ws4[t + i * 256] = wg[t + i * 256];
            }
            __syncthreads();
#pragma unroll 4
            for (int k = 0; k < 64; k++) {
                float xv[4];
#pragma unroll
                for (int i = 0; i < 4; i++)
                    xv[i] = xs[(4 * tr + i) * PR_INDIM + kb + k];
                float wv[8];
#pragma unroll
                for (int c = 0; c < 8; c++)
                    wv[c] = ws[k * PR_D + tc + 16 * c];
#pragma unroll
                for (int i = 0; i < 4; i++)
#pragma unroll
                    for (int c = 0; c < 8; c++)
                        acc[i][c] = fmaf(xv[i], wv[c], acc[i][c]);
            }
        }

        __syncthreads();
#pragma unroll
        for (int i = 0; i < 4; i++)
#pragma unroll
            for (int c = 0; c < 8; c++)
                ws[(4 * tr + i) * 132 + tc + 16 * c] = acc[i][c];
        __syncthreads();

        if (m < 2) {
            __half* Dh = (m == 0) ? g_Qhi : g_Khi;
            __half* Dl = (m == 0) ? g_Qlo : g_Klo;
            const int r  = t >> 2;
            const int cb = (t & 3) * 32;
            uint32_t hi[16], lo[16];
#pragma unroll
            for (int j = 0; j < 16; j++)
                split2h(ws[r * 132 + cb + 2 * j], ws[r * 132 + cb + 2 * j + 1], hi[j], lo[j]);
            uint4* dh = (uint4*)(Dh + (size_t)(rb + r) * PR_D + cb);
            uint4* dl = (uint4*)(Dl + (size_t)(rb + r) * PR_D + cb);
#pragma unroll
            for (int q = 0; q < 4; q++) {
                dh[q] = make_uint4(hi[4*q], hi[4*q+1], hi[4*q+2], hi[4*q+3]);
                dl[q] = make_uint4(lo[4*q], lo[4*q+1], lo[4*q+2], lo[4*q+3]);
            }
        } else {
            // V: transpose to [d][n], single fp16
            const int d    = t >> 1;
            const int half = t & 1;
            uint32_t hv[16];
#pragma unroll
            for (int j = 0; j < 16; j++) {
                int k0 = 32 * half + 2 * j;
                hv[j] = pack_f16x2(ws[k0 * 132 + d], ws[(k0 + 1) * 132 + d]);
            }
            uint4* dv = (uint4*)(g_VTh + (size_t)d * PR_N + rb + 32 * half);
#pragma unroll
            for (int q = 0; q < 4; q++)
                dv[q] = make_uint4(hv[4*q], hv[4*q+1], hv[4*q+2], hv[4*q+3]);
        }
        __syncthreads();
    }
}

// ---------------------------------------------------------------------------
// Kernel 2: HMMA flash attention.
//   S  = Q K^T : 3-pass split fp16 (hi*hi + lo*hi + hi*lo), error ~2^-24
//   softmax    : per-row running max (flash), P = exp(z - m) in (0,1]
//   O += P V   : single-pass fp16 (P fp16, V fp16), error ~2^-12 random
// 4-stage cp.async pipeline over 64-key subtiles, Q frags register-resident.
// grid = 128 CTAs x 256 thr; warp w owns q rows [16w, 16w+16).
// ---------------------------------------------------------------------------
#define KROW   272                 // K row bytes (128 fp16 + pad)
#define VROW   144                 // VT row bytes (64 fp16 + pad)
#define OFF_KH 0
#define OFF_KL 17408
#define OFF_VH 34816
#define ST_BYTES 53248
#define N_STAGES 4
#define SM_BYTES (N_STAGES * ST_BYTES)   // 212992
#define NT (PR_N / 64)

__device__ __forceinline__ void load_stage(uint32_t dst, int kb)
{
    const int t = threadIdx.x;
#pragma unroll
    for (int i = 0; i < 4; i++) {
        int cid = t + i * 256;               // 1024: 64 rows x 16 chunks
        int r = cid >> 4, c = cid & 15;
        cp16(dst + OFF_KH + r * KROW + c * 16, g_Khi + (size_t)(kb + r) * PR_D + c * 8);
        cp16(dst + OFF_KL + r * KROW + c * 16, g_Klo + (size_t)(kb + r) * PR_D + c * 8);
    }
#pragma unroll
    for (int i = 0; i < 4; i++) {
        int cid = t + i * 256;               // 1024: 128 rows x 8 chunks
        int r = cid >> 3, c = cid & 7;
        cp16(dst + OFF_VH + r * VROW + c * 16, g_VTh + (size_t)r * PR_N + kb + c * 8);
    }
}

__global__ void __launch_bounds__(256, 1) pr_attn_mma(float* __restrict__ out)
{
    extern __shared__ char sm[];
    const uint32_t sb = smem_u32(sm);

    const int t    = threadIdx.x;
    const int w    = t >> 5;
    const int lane = t & 31;
    const int qb   = blockIdx.x * 128;

    const uint32_t aRow = (uint32_t)(16 * w + (lane & 15));
    const uint32_t aCol = (uint32_t)(lane >> 4);
    const uint32_t bRow = (uint32_t)((lane & 7) + 8 * (lane >> 4));
    const uint32_t bCol = (uint32_t)((lane >> 3) & 1);
    const uint32_t bKoff = bRow * KROW + bCol * 16;
    const uint32_t bVoff = bRow * VROW + bCol * 16;

    // ---- stage Q and grab fragments (Qhi at sb, Qlo at sb+34816) ----
    {
#pragma unroll
        for (int i = 0; i < 8; i++) {
            int cid = t + i * 256;
            int r = cid >> 4, c = cid & 15;
            cp16(sb + r * KROW + c * 16,         g_Qhi + (size_t)(qb + r) * PR_D + c * 8);
            cp16(sb + 34816 + r * KROW + c * 16, g_Qlo + (size_t)(qb + r) * PR_D + c * 8);
        }
        cp_commit();
        cp_wait0();
        __syncthreads();
    }
    uint32_t qh[8][4], ql[8][4];
    {
        const uint32_t aQ = sb + aRow * KROW + aCol * 16;
#pragma unroll
        for (int kc = 0; kc < 8; kc++) {
            ldmx4(qh[kc], aQ + kc * 32);
            ldmx4(ql[kc], aQ + 34816 + kc * 32);
        }
    }
    __syncthreads();

    float o[16][4];
#pragma unroll
    for (int i = 0; i < 16; i++)
#pragma unroll
        for (int j = 0; j < 4; j++) o[i][j] = 0.0f;
    float lsum0 = 0.0f, lsum1 = 0.0f;
    float M0 = -1e30f, M1 = -1e30f;

    // prefetch tiles 0,1,2
    load_stage(sb + 0 * ST_BYTES, 0);
    cp_commit();
    load_stage(sb + 1 * ST_BYTES, 64);
    cp_commit();
    load_stage(sb + 2 * ST_BYTES, 128);
    cp_commit();

    int st_cur = 0, st_pre = 3;
#pragma unroll 1
    for (int tt = 0; tt < NT; tt++) {
        __syncthreads();                 // prefetch target free of readers
        if (tt + 3 < NT) load_stage(sb + st_pre * ST_BYTES, (tt + 3) * 64);
        cp_commit();
        cp_wait3();                      // oldest (tile tt) arrived
        __syncthreads();

        const uint32_t p   = sb + st_cur * ST_BYTES;
        const uint32_t bKh = p + OFF_KH + bKoff;
        const uint32_t bKl = p + OFF_KL + bKoff;
        const uint32_t bVh = p + OFF_VH + bVoff;

        // ---- S = Q K^T (qh*kh + ql*kh + qh*kl), 64 keys ----
        float s[8][4];
#pragma unroll
        for (int i = 0; i < 8; i++)
#pragma unroll
            for (int j = 0; j < 4; j++) s[i][j] = 0.0f;

        uint32_t bh[2][4], bl[2][4];
        ldmx4(bh[0], bKh);
        ldmx4(bl[0], bKl);
#pragma unroll
        for (int idx = 0; idx < 32; idx++) {
            const int cur = idx & 1, nxt = cur ^ 1;
            if (idx < 31) {
                const int kc2 = (idx + 1) >> 2, jn2 = (idx + 1) & 3;
                ldmx4(bh[nxt], bKh + jn2 * (16 * KROW) + kc2 * 32);
                ldmx4(bl[nxt], bKl + jn2 * (16 * KROW) + kc2 * 32);
            }
            const int kc = idx >> 2, jn = idx & 3;
            mma16816h(s[2 * jn],     qh[kc], &bh[cur][0]);
            mma16816h(s[2 * jn + 1], qh[kc], &bh[cur][2]);
            mma16816h(s[2 * jn],     ql[kc], &bh[cur][0]);
            mma16816h(s[2 * jn + 1], ql[kc], &bh[cur][2]);
            mma16816h(s[2 * jn],     qh[kc], &bl[cur][0]);
            mma16816h(s[2 * jn + 1], qh[kc], &bl[cur][2]);
        }

        // ---- flash softmax: running max, P = exp(z - M) in fp16 ----
        float m0 = -1e30f, m1 = -1e30f;
#pragma unroll
        for (int jt = 0; jt < 8; jt++) {
            m0 = fmaxf(m0, fmaxf(s[jt][0], s[jt][1]));
            m1 = fmaxf(m1, fmaxf(s[jt][2], s[jt][3]));
        }
        m0 = fmaxf(m0, __shfl_xor_sync(0xffffffffu, m0, 1));
        m0 = fmaxf(m0, __shfl_xor_sync(0xffffffffu, m0, 2));
        m1 = fmaxf(m1, __shfl_xor_sync(0xffffffffu, m1, 1));
        m1 = fmaxf(m1, __shfl_xor_sync(0xffffffffu, m1, 2));
        const float M0n = fmaxf(M0, m0), M1n = fmaxf(M1, m1);
        const float sc0 = ex2f((M0 - M0n) * LOG2E);
        const float sc1 = ex2f((M1 - M1n) * LOG2E);
        M0 = M0n; M1 = M1n;
        const float b0 = M0 * LOG2E, b1 = M1 * LOG2E;

        float ts0 = 0.0f, ts1 = 0.0f;
        uint32_t pp[16];
#pragma unroll
        for (int jt = 0; jt < 8; jt++) {
            float e0 = ex2f(fmaf(s[jt][0], LOG2E, -b0));
            float e1 = ex2f(fmaf(s[jt][1], LOG2E, -b0));
            float e2 = ex2f(fmaf(s[jt][2], LOG2E, -b1));
            float e3 = ex2f(fmaf(s[jt][3], LOG2E, -b1));
            ts0 += e0 + e1;
            ts1 += e2 + e3;
            pp[2 * jt]     = pack_f16x2(e0, e1);
            pp[2 * jt + 1] = pack_f16x2(e2, e3);
        }
        lsum0 = lsum0 * sc0 + ts0;
        lsum1 = lsum1 * sc1 + ts1;
#pragma unroll
        for (int dt = 0; dt < 16; dt++) {
            o[dt][0] *= sc0; o[dt][1] *= sc0;
            o[dt][2] *= sc1; o[dt][3] *= sc1;
        }

        // ---- O += P V (single-pass fp16), k = 64 keys ----
        uint32_t v[2][4];
        ldmx4(v[0], bVh);
#pragma unroll
        for (int idx = 0; idx < 32; idx++) {
            const int cur = idx & 1, nxt = cur ^ 1;
            if (idx < 31) {
                const int kc2 = (idx + 1) >> 3, dn2 = (idx + 1) & 7;
                ldmx4(v[nxt], bVh + dn2 * (16 * VROW) + kc2 * 32);
            }
            const int kc = idx >> 3, dn = idx & 7;
            mma16816h(o[2 * dn],     &pp[4 * kc], &v[cur][0]);
            mma16816h(o[2 * dn + 1], &pp[4 * kc], &v[cur][2]);
        }

        st_cur = (st_cur + 1) & 3;
        st_pre = (st_pre + 1) & 3;
    }

    // ---- reduce row sums over the 4 lanes sharing each row ----
    lsum0 += __shfl_xor_sync(0xffffffffu, lsum0, 1);
    lsum0 += __shfl_xor_sync(0xffffffffu, lsum0, 2);
    lsum1 += __shfl_xor_sync(0xffffffffu, lsum1, 1);
    lsum1 += __shfl_xor_sync(0xffffffffu, lsum1, 2);
    const float inv0 = 1.0f / lsum0;
    const float inv1 = 1.0f / lsum1;

    const int r0 = qb + 16 * w + (lane >> 2);
    const int cb = 2 * (lane & 3);
#pragma unroll
    for (int dt = 0; dt < 16; dt++) {
        float2 v0 = make_float2(o[dt][0] * inv0, o[dt][1] * inv0);
        float2 v1 = make_float2(o[dt][2] * inv1, o[dt][3] * inv1);
        *(float2*)(out + (size_t)r0 * PR_D + 8 * dt + cb)       = v0;
        *(float2*)(out + (size_t)(r0 + 8) * PR_D + 8 * dt + cb) = v1;
    }
}

// ---------------------------------------------------------------------------
extern "C" void kernel_launch(void* const* d_in, const int* in_sizes, int n_in,
                              void* d_out, int out_size)
{
    const float* x  = (const float*)d_in[0];
    const float* Wq = (const float*)d_in[1];
    const float* bq = (const float*)d_in[2];
    const float* Wk = (const float*)d_in[3];
    const float* bk = (const float*)d_in[4];
    const float* Wv = (const float*)d_in[5];
    const float* bv = (const float*)d_in[6];
    float* out = (float*)d_out;

    pr_proj_kernel<<<PR_N / 64, 256>>>(x, Wq, bq, Wk, bk, Wv, bv);

    cudaFuncSetAttribute(pr_attn_mma,
                         cudaFuncAttributeMaxDynamicSharedMemorySize, SM_BYTES);
    pr_attn_mma<<<PR_N / 128, 256, SM_BYTES>>>(out);
}

// round 7
// speedup vs baseline: 5.1614x; 1.0150x over previous
#include <cuda_runtime.h>
#include <cuda_fp16.h>
#include <cstdint>
#include <cstddef>

#define PR_N      16384
#define PR_INDIM  256
#define PR_D      128
#define LOG2E     1.4426950408889634f

// ---------------- fp16 split scratch (hi+lo ~= 22-bit mantissa) -------------
__device__ __align__(16) __half g_Qhi[PR_N * PR_D];
__device__ __align__(16) __half g_Qlo[PR_N * PR_D];
__device__ __align__(16) __half g_Khi[PR_N * PR_D];
__device__ __align__(16) __half g_Klo[PR_N * PR_D];
__device__ __align__(16) __half g_VTh[PR_D * PR_N];   // V transposed [d][n], fp16

// ---------------- helpers ---------------------------------------------------
__device__ __forceinline__ uint32_t smem_u32(const void* p) {
    uint32_t a;
    asm("{ .reg .u64 t; cvta.to.shared.u64 t, %1; cvt.u32.u64 %0, t; }"
        : "=r"(a) : "l"(p));
    return a;
}
__device__ __forceinline__ float ex2f(float x) {   // MUFU.EX2
    float r;
    asm("ex2.approx.ftz.f32 %0, %1;" : "=f"(r) : "f"(x));
    return r;
}
// pack two fp32 -> fp16x2 (a low half, b high half)
__device__ __forceinline__ uint32_t pack_f16x2(float a, float b) {
    uint32_t r;
    asm("cvt.rn.f16x2.f32 %0, %1, %2;" : "=r"(r) : "f"(b), "f"(a));
    return r;
}
__device__ __forceinline__ void split2h(float f0, float f1, uint32_t& hi, uint32_t& lo) {
    __half a0 = __float2half_rn(f0), a1 = __float2half_rn(f1);
    hi = ((uint32_t)__half_as_ushort(a1) << 16) | __half_as_ushort(a0);
    lo = pack_f16x2(f0 - __half2float(a0), f1 - __half2float(a1));
}
__device__ __forceinline__ void ldmx4(uint32_t* r, uint32_t addr) {
    asm volatile("ldmatrix.sync.aligned.m8n8.x4.shared.b16 {%0,%1,%2,%3}, [%4];"
                 : "=r"(r[0]), "=r"(r[1]), "=r"(r[2]), "=r"(r[3]) : "r"(addr));
}
__device__ __forceinline__ void mma16816h(float* c, const uint32_t* a,
                                          const uint32_t* b) {
    asm volatile(
        "mma.sync.aligned.m16n8k16.row.col.f32.f16.f16.f32 "
        "{%0,%1,%2,%3}, {%4,%5,%6,%7}, {%8,%9}, {%0,%1,%2,%3};"
        : "+f"(c[0]), "+f"(c[1]), "+f"(c[2]), "+f"(c[3])
        : "r"(a[0]), "r"(a[1]), "r"(a[2]), "r"(a[3]), "r"(b[0]), "r"(b[1]));
}
__device__ __forceinline__ void cp16(uint32_t dst, const void* src) {
    asm volatile("cp.async.cg.shared.global [%0], [%1], 16;"
                 :: "r"(dst), "l"(src) : "memory");
}
__device__ __forceinline__ void cp_commit() {
    asm volatile("cp.async.commit_group;" ::: "memory");
}
__device__ __forceinline__ void cp_wait3() {
    asm volatile("cp.async.wait_group 3;" ::: "memory");
}
__device__ __forceinline__ void cp_wait0() {
    asm volatile("cp.async.wait_group 0;" ::: "memory");
}

// ---------------------------------------------------------------------------
// Kernel 1: QKV projection + fp16 split + V transpose.  grid=256, block=256.
// ---------------------------------------------------------------------------
__global__ void __launch_bounds__(256) pr_proj_kernel(
    const float* __restrict__ x,
    const float* __restrict__ Wq, const float* __restrict__ bq,
    const float* __restrict__ Wk, const float* __restrict__ bk,
    const float* __restrict__ Wv, const float* __restrict__ bv)
{
    __shared__ float xs[64 * PR_INDIM];
    __shared__ float ws[64 * 132];

    const int t  = threadIdx.x;
    const int rb = blockIdx.x * 64;
    const int tr = t >> 4;
    const int tc = t & 15;

    {
        const float4* xg  = (const float4*)(x + (size_t)rb * PR_INDIM);
        float4*       xs4 = (float4*)xs;
#pragma unroll
        for (int i = 0; i < 16; i++) xs4[t + i * 256] = xg[t + i * 256];
    }

    const float* Wm[3] = {Wq, Wk, Wv};
    const float* bm[3] = {bq, bk, bv};

#pragma unroll 1
    for (int m = 0; m < 3; m++) {
        float acc[4][8];
#pragma unroll
        for (int c = 0; c < 8; c++) {
            float b = bm[m][tc + 16 * c];
#pragma unroll
            for (int i = 0; i < 4; i++) acc[i][c] = b;
        }

        for (int kb = 0; kb < PR_INDIM; kb += 64) {
            __syncthreads();
            {
                const float4* wg  = (const float4*)(Wm[m] + (size_t)kb * PR_D);
                float4*       ws4 = (float4*)ws;
#pragma unroll
                for (int i = 0; i < 8; i++) ws4[t + i * 256] = wg[t + i * 256];
            }
            __syncthreads();
#pragma unroll 4
            for (int k = 0; k < 64; k++) {
                float xv[4];
#pragma unroll
                for (int i = 0; i < 4; i++)
                    xv[i] = xs[(4 * tr + i) * PR_INDIM + kb + k];
                float wv[8];
#pragma unroll
                for (int c = 0; c < 8; c++)
                    wv[c] = ws[k * PR_D + tc + 16 * c];
#pragma unroll
                for (int i = 0; i < 4; i++)
#pragma unroll
                    for (int c = 0; c < 8; c++)
                        acc[i][c] = fmaf(xv[i], wv[c], acc[i][c]);
            }
        }

        __syncthreads();
#pragma unroll
        for (int i = 0; i < 4; i++)
#pragma unroll
            for (int c = 0; c < 8; c++)
                ws[(4 * tr + i) * 132 + tc + 16 * c] = acc[i][c];
        __syncthreads();

        if (m < 2) {
            __half* Dh = (m == 0) ? g_Qhi : g_Khi;
            __half* Dl = (m == 0) ? g_Qlo : g_Klo;
            const int r  = t >> 2;
            const int cb = (t & 3) * 32;
            uint32_t hi[16], lo[16];
#pragma unroll
            for (int j = 0; j < 16; j++)
                split2h(ws[r * 132 + cb + 2 * j], ws[r * 132 + cb + 2 * j + 1], hi[j], lo[j]);
            uint4* dh = (uint4*)(Dh + (size_t)(rb + r) * PR_D + cb);
            uint4* dl = (uint4*)(Dl + (size_t)(rb + r) * PR_D + cb);
#pragma unroll
            for (int q = 0; q < 4; q++) {
                dh[q] = make_uint4(hi[4*q], hi[4*q+1], hi[4*q+2], hi[4*q+3]);
                dl[q] = make_uint4(lo[4*q], lo[4*q+1], lo[4*q+2], lo[4*q+3]);
            }
        } else {
            // V: transpose to [d][n], single fp16
            const int d    = t >> 1;
            const int half = t & 1;
            uint32_t hv[16];
#pragma unroll
            for (int j = 0; j < 16; j++) {
                int k0 = 32 * half + 2 * j;
                hv[j] = pack_f16x2(ws[k0 * 132 + d], ws[(k0 + 1) * 132 + d]);
            }
            uint4* dv = (uint4*)(g_VTh + (size_t)d * PR_N + rb + 32 * half);
#pragma unroll
            for (int q = 0; q < 4; q++)
                dv[q] = make_uint4(hv[4*q], hv[4*q+1], hv[4*q+2], hv[4*q+3]);
        }
        __syncthreads();
    }
}

// ---------------------------------------------------------------------------
// Kernel 2: HMMA flash attention.
//   S  = Q K^T : 3-pass split fp16, issued as 3 independent 8-MMA waves per
//                kc so same-accumulator MMAs are >=8 issues apart (RAW-free)
//   softmax    : running max, rescale only when the max actually increases
//   O += P V   : single-pass fp16
// 4-stage cp.async pipeline over 64-key subtiles, Q frags register-resident.
// grid = 128 CTAs x 256 thr; warp w owns q rows [16w, 16w+16).
// ---------------------------------------------------------------------------
#define KROW   272                 // K row bytes (128 fp16 + pad)
#define VROW   144                 // VT row bytes (64 fp16 + pad)
#define OFF_KH 0
#define OFF_KL 17408
#define OFF_VH 34816
#define ST_BYTES 53248
#define N_STAGES 4
#define SM_BYTES (N_STAGES * ST_BYTES)   // 212992
#define NT (PR_N / 64)

__device__ __forceinline__ void load_stage(uint32_t dst, int kb)
{
    const int t = threadIdx.x;
#pragma unroll
    for (int i = 0; i < 4; i++) {
        int cid = t + i * 256;               // 1024: 64 rows x 16 chunks
        int r = cid >> 4, c = cid & 15;
        cp16(dst + OFF_KH + r * KROW + c * 16, g_Khi + (size_t)(kb + r) * PR_D + c * 8);
        cp16(dst + OFF_KL + r * KROW + c * 16, g_Klo + (size_t)(kb + r) * PR_D + c * 8);
    }
#pragma unroll
    for (int i = 0; i < 4; i++) {
        int cid = t + i * 256;               // 1024: 128 rows x 8 chunks
        int r = cid >> 3, c = cid & 7;
        cp16(dst + OFF_VH + r * VROW + c * 16, g_VTh + (size_t)r * PR_N + kb + c * 8);
    }
}

__global__ void __launch_bounds__(256, 1) pr_attn_mma(float* __restrict__ out)
{
    extern __shared__ char sm[];
    const uint32_t sb = smem_u32(sm);

    const int t    = threadIdx.x;
    const int w    = t >> 5;
    const int lane = t & 31;
    const int qb   = blockIdx.x * 128;

    const uint32_t aRow = (uint32_t)(16 * w + (lane & 15));
    const uint32_t aCol = (uint32_t)(lane >> 4);
    const uint32_t bRow = (uint32_t)((lane & 7) + 8 * (lane >> 4));
    const uint32_t bCol = (uint32_t)((lane >> 3) & 1);
    const uint32_t bKoff = bRow * KROW + bCol * 16;
    const uint32_t bVoff = bRow * VROW + bCol * 16;

    // ---- stage Q and grab fragments (Qhi at sb, Qlo at sb+34816) ----
    {
#pragma unroll
        for (int i = 0; i < 8; i++) {
            int cid = t + i * 256;
            int r = cid >> 4, c = cid & 15;
            cp16(sb + r * KROW + c * 16,         g_Qhi + (size_t)(qb + r) * PR_D + c * 8);
            cp16(sb + 34816 + r * KROW + c * 16, g_Qlo + (size_t)(qb + r) * PR_D + c * 8);
        }
        cp_commit();
        cp_wait0();
        __syncthreads();
    }
    uint32_t qh[8][4], ql[8][4];
    {
        const uint32_t aQ = sb + aRow * KROW + aCol * 16;
#pragma unroll
        for (int kc = 0; kc < 8; kc++) {
            ldmx4(qh[kc], aQ + kc * 32);
            ldmx4(ql[kc], aQ + 34816 + kc * 32);
        }
    }
    __syncthreads();

    float o[16][4];
#pragma unroll
    for (int i = 0; i < 16; i++)
#pragma unroll
        for (int j = 0; j < 4; j++) o[i][j] = 0.0f;
    float lsum0 = 0.0f, lsum1 = 0.0f;
    float M0 = -1e30f, M1 = -1e30f;

    // prefetch tiles 0,1,2
    load_stage(sb + 0 * ST_BYTES, 0);
    cp_commit();
    load_stage(sb + 1 * ST_BYTES, 64);
    cp_commit();
    load_stage(sb + 2 * ST_BYTES, 128);
    cp_commit();

    int st_cur = 0, st_pre = 3;
#pragma unroll 1
    for (int tt = 0; tt < NT; tt++) {
        __syncthreads();                 // prefetch target free of readers
        if (tt + 3 < NT) load_stage(sb + st_pre * ST_BYTES, (tt + 3) * 64);
        cp_commit();
        cp_wait3();                      // oldest (tile tt) arrived
        __syncthreads();

        const uint32_t p   = sb + st_cur * ST_BYTES;
        const uint32_t bKh = p + OFF_KH + bKoff;
        const uint32_t bKl = p + OFF_KL + bKoff;
        const uint32_t bVh = p + OFF_VH + bVoff;

        // ---- S = Q K^T (qh*kh + ql*kh + qh*kl), 64 keys ----
        float s[8][4];
#pragma unroll
        for (int i = 0; i < 8; i++)
#pragma unroll
            for (int j = 0; j < 4; j++) s[i][j] = 0.0f;

#pragma unroll
        for (int kc = 0; kc < 8; kc++) {
            uint32_t bh[4][4], bl[4][4];
#pragma unroll
            for (int jn = 0; jn < 4; jn++) {
                ldmx4(bh[jn], bKh + jn * (16 * KROW) + kc * 32);
                ldmx4(bl[jn], bKl + jn * (16 * KROW) + kc * 32);
            }
            // three waves of 8 independent MMAs: no accumulator reused
            // within a wave, reuse distance >= 8 issues
#pragma unroll
            for (int jn = 0; jn < 4; jn++) {
                mma16816h(s[2 * jn],     qh[kc], &bh[jn][0]);
                mma16816h(s[2 * jn + 1], qh[kc], &bh[jn][2]);
            }
#pragma unroll
            for (int jn = 0; jn < 4; jn++) {
                mma16816h(s[2 * jn],     ql[kc], &bh[jn][0]);
                mma16816h(s[2 * jn + 1], ql[kc], &bh[jn][2]);
            }
#pragma unroll
            for (int jn = 0; jn < 4; jn++) {
                mma16816h(s[2 * jn],     qh[kc], &bl[jn][0]);
                mma16816h(s[2 * jn + 1], qh[kc], &bl[jn][2]);
            }
        }

        // ---- flash softmax: running max, rescale only on max increase ----
        float m0 = s[0][0], m1 = s[0][2];
#pragma unroll
        for (int jt = 0; jt < 8; jt++) {
            m0 = fmaxf(m0, fmaxf(s[jt][0], s[jt][1]));
            m1 = fmaxf(m1, fmaxf(s[jt][2], s[jt][3]));
        }
        m0 = fmaxf(m0, __shfl_xor_sync(0xffffffffu, m0, 1));
        m0 = fmaxf(m0, __shfl_xor_sync(0xffffffffu, m0, 2));
        m1 = fmaxf(m1, __shfl_xor_sync(0xffffffffu, m1, 1));
        m1 = fmaxf(m1, __shfl_xor_sync(0xffffffffu, m1, 2));

        if (m0 > M0 || m1 > M1) {        // rare after the first few tiles
            const float M0n = fmaxf(M0, m0), M1n = fmaxf(M1, m1);
            const float sc0 = ex2f((M0 - M0n) * LOG2E);
            const float sc1 = ex2f((M1 - M1n) * LOG2E);
            M0 = M0n; M1 = M1n;
            lsum0 *= sc0;
            lsum1 *= sc1;
#pragma unroll
            for (int dt = 0; dt < 16; dt++) {
                o[dt][0] *= sc0; o[dt][1] *= sc0;
                o[dt][2] *= sc1; o[dt][3] *= sc1;
            }
        }
        const float b0 = M0 * LOG2E, b1 = M1 * LOG2E;

        float ts0 = 0.0f, ts1 = 0.0f;
        uint32_t pp[16];
#pragma unroll
        for (int jt = 0; jt < 8; jt++) {
            float e0 = ex2f(fmaf(s[jt][0], LOG2E, -b0));
            float e1 = ex2f(fmaf(s[jt][1], LOG2E, -b0));
            float e2 = ex2f(fmaf(s[jt][2], LOG2E, -b1));
            float e3 = ex2f(fmaf(s[jt][3], LOG2E, -b1));
            ts0 += e0 + e1;
            ts1 += e2 + e3;
            pp[2 * jt]     = pack_f16x2(e0, e1);
            pp[2 * jt + 1] = pack_f16x2(e2, e3);
        }
        lsum0 += ts0;
        lsum1 += ts1;

        // ---- O += P V (single-pass fp16), k = 64 keys ----
        uint32_t v[2][4];
        ldmx4(v[0], bVh);
#pragma unroll
        for (int idx = 0; idx < 32; idx++) {
            const int cur = idx & 1, nxt = cur ^ 1;
            if (idx < 31) {
                const int kc2 = (idx + 1) >> 3, dn2 = (idx + 1) & 7;
                ldmx4(v[nxt], bVh + dn2 * (16 * VROW) + kc2 * 32);
            }
            const int kc = idx >> 3, dn = idx & 7;
            mma16816h(o[2 * dn],     &pp[4 * kc], &v[cur][0]);
            mma16816h(o[2 * dn + 1], &pp[4 * kc], &v[cur][2]);
        }

        st_cur = (st_cur + 1) & 3;
        st_pre = (st_pre + 1) & 3;
    }

    // ---- reduce row sums over the 4 lanes sharing each row ----
    lsum0 += __shfl_xor_sync(0xffffffffu, lsum0, 1);
    lsum0 += __shfl_xor_sync(0xffffffffu, lsum0, 2);
    lsum1 += __shfl_xor_sync(0xffffffffu, lsum1, 1);
    lsum1 += __shfl_xor_sync(0xffffffffu, lsum1, 2);
    const float inv0 = 1.0f / lsum0;
    const float inv1 = 1.0f / lsum1;

    const int r0 = qb + 16 * w + (lane >> 2);
    const int cb = 2 * (lane & 3);
#pragma unroll
    for (int dt = 0; dt < 16; dt++) {
        float2 v0 = make_float2(o[dt][0] * inv0, o[dt][1] * inv0);
        float2 v1 = make_float2(o[dt][2] * inv1, o[dt][3] * inv1);
        *(float2*)(out + (size_t)r0 * PR_D + 8 * dt + cb)       = v0;
        *(float2*)(out + (size_t)(r0 + 8) * PR_D + 8 * dt + cb) = v1;
    }
}

// ---------------------------------------------------------------------------
extern "C" void kernel_launch(void* const* d_in, const int* in_sizes, int n_in,
                              void* d_out, int out_size)
{
    const float* x  = (const float*)d_in[0];
    const float* Wq = (const float*)d_in[1];
    const float* bq = (const float*)d_in[2];
    const float* Wk = (const float*)d_in[3];
    const float* bk = (const float*)d_in[4];
    const float* Wv = (const float*)d_in[5];
    const float* bv = (const float*)d_in[6];
    float* out = (float*)d_out;

    pr_proj_kernel<<<PR_N / 64, 256>>>(x, Wq, bq, Wk, bk, Wv, bv);

    cudaFuncSetAttribute(pr_attn_mma,
                         cudaFuncAttributeMaxDynamicSharedMemorySize, SM_BYTES);
    pr_attn_mma<<<PR_N / 128, 256, SM_BYTES>>>(out);
}